// round 15
// baseline (speedup 1.0000x reference)
#include <cuda_runtime.h>
#include <cuda_bf16.h>
#include <math.h>
#include <stdint.h>

#define BB 2
#define SS 4096
#define DD 768
#define HH 12
#define DHH 64
#define W1C 256
#define MTOK (BB*SS)   // 8192
#define WSZ (DD*DD)

typedef __nv_bfloat16 bf16;

// ---------------- scratch (device globals; no allocation allowed) ----------------
__device__ __align__(16) float g_x [MTOK*DD];
__device__ __align__(16) float g_h [MTOK*DD];
__device__ __align__(16) bf16  g_xb [MTOK*DD];
__device__ __align__(16) bf16  g_qb [MTOK*DD];
__device__ __align__(16) bf16  g_kb [MTOK*DD];
__device__ __align__(16) bf16  g_vb [MTOK*DD];
__device__ __align__(16) bf16  g_cb [MTOK*DD];
__device__ __align__(16) bf16  g_wt [4*WSZ];

// ---------------- fused: embedding+LN (warp/token) | weight transpose ----------------
#define EMB_BLOCKS (MTOK / 8)    // 1024 (8 warps = 8 tokens per block)
#define WT_BLOCKS  (24*24*4)     // 2304

__global__ __launch_bounds__(256) void embed_wtrans_kernel(
    const int* __restrict__ ids, const float* __restrict__ wemb,
    const float* __restrict__ pemb, const float* __restrict__ g,
    const float* __restrict__ b, float* __restrict__ x, bf16* __restrict__ xb,
    const float* __restrict__ W0, const float* __restrict__ W1,
    const float* __restrict__ W2, const float* __restrict__ W3,
    bf16* __restrict__ wt)
{
    __shared__ float tile[32][33];
    const int lane = threadIdx.x & 31;
    const int wid  = threadIdx.x >> 5;
    if (blockIdx.x < EMB_BLOCKS) {
        int tok = blockIdx.x * 8 + wid;
        int s_pos = tok & (SS - 1);
        int id = ids[tok];
        const float* we = wemb + (size_t)id * DD;
        const float* pe = pemb + (size_t)s_pos * DD;
        float v[24]; float sum = 0.f, sum2 = 0.f;
        #pragma unroll
        for (int i = 0; i < 24; i++) {
            int d = lane + i * 32;
            v[i] = we[d] + pe[d];
            sum += v[i]; sum2 += v[i] * v[i];
        }
        #pragma unroll
        for (int o = 16; o > 0; o >>= 1) {
            sum  += __shfl_xor_sync(0xffffffffu, sum,  o);
            sum2 += __shfl_xor_sync(0xffffffffu, sum2, o);
        }
        float mean = sum * (1.0f / DD);
        float var  = sum2 * (1.0f / DD) - mean * mean;
        float rstd = rsqrtf(var + 1e-5f);
        float* row = x + (size_t)tok * DD;
        bf16*  rowb = xb + (size_t)tok * DD;
        #pragma unroll
        for (int i = 0; i < 24; i++) {
            int d = lane + i * 32;
            float o = (v[i] - mean) * rstd * g[d] + b[d];
            row[d] = o;
            rowb[d] = __float2bfloat16(o);
        }
    } else {
        int bx = blockIdx.x - EMB_BLOCKS;
        int w  = bx / 576;
        int rem = bx % 576;
        int k0 = (rem / 24) * 32;
        int n0 = (rem % 24) * 32;
        const float* W = (w == 0) ? W0 : (w == 1) ? W1 : (w == 2) ? W2 : W3;
        bf16* dst = wt + (size_t)w * WSZ;
        int tx = lane, ty = wid;
        #pragma unroll
        for (int i = 0; i < 4; i++)
            tile[ty + i * 8][tx] = W[(size_t)(k0 + ty + i * 8) * DD + n0 + tx];
        __syncthreads();
        #pragma unroll
        for (int i = 0; i < 4; i++)
            dst[(size_t)(n0 + ty + i * 8) * DD + k0 + tx] = __float2bfloat16(tile[tx][ty + i * 8]);
    }
}

// ---------------- final layernorm (warp per token) ----------------
__global__ __launch_bounds__(256) void ln_kernel(
    const float* __restrict__ in, const float* __restrict__ g,
    const float* __restrict__ b, float* __restrict__ out)
{
    const int lane = threadIdx.x & 31;
    const int wid  = threadIdx.x >> 5;
    int tok = blockIdx.x * 8 + wid;
    const float* row = in + (size_t)tok * DD;
    float v[24]; float sum = 0.f, sum2 = 0.f;
    #pragma unroll
    for (int i = 0; i < 24; i++) {
        int d = lane + i * 32;
        v[i] = row[d];
        sum += v[i]; sum2 += v[i] * v[i];
    }
    #pragma unroll
    for (int o = 16; o > 0; o >>= 1) {
        sum  += __shfl_xor_sync(0xffffffffu, sum,  o);
        sum2 += __shfl_xor_sync(0xffffffffu, sum2, o);
    }
    float mean = sum * (1.0f / DD);
    float var  = sum2 * (1.0f / DD) - mean * mean;
    float rstd = rsqrtf(var + 1e-5f);
    float* orow = out + (size_t)tok * DD;
    #pragma unroll
    for (int i = 0; i < 24; i++) {
        int d = lane + i * 32;
        orow[d] = (v[i] - mean) * rstd * g[d] + b[d];
    }
}

// ---------------- async copy + mma + ldmatrix helpers ----------------
__device__ __forceinline__ void cp16(uint32_t smem, const void* gmem) {
    asm volatile("cp.async.cg.shared.global [%0], [%1], 16;\n" :: "r"(smem), "l"(gmem));
}
__device__ __forceinline__ void cp_commit() { asm volatile("cp.async.commit_group;\n"); }
template<int N>
__device__ __forceinline__ void cp_wait() { asm volatile("cp.async.wait_group %0;\n" :: "n"(N)); }

__device__ __forceinline__ void mma_bf16(float* c, const uint32_t* a, const uint32_t* b) {
    asm volatile(
        "mma.sync.aligned.m16n8k16.row.col.f32.bf16.bf16.f32 "
        "{%0,%1,%2,%3}, {%4,%5,%6,%7}, {%8,%9}, {%0,%1,%2,%3};\n"
        : "+f"(c[0]), "+f"(c[1]), "+f"(c[2]), "+f"(c[3])
        : "r"(a[0]), "r"(a[1]), "r"(a[2]), "r"(a[3]), "r"(b[0]), "r"(b[1]));
}
__device__ __forceinline__ uint32_t packbf(float x, float y) {
    __nv_bfloat162 h = __floats2bfloat162_rn(x, y);
    return *(uint32_t*)&h;
}
__device__ __forceinline__ float ex2(float x) {
    float r;
    asm("ex2.approx.f32 %0, %1;" : "=f"(r) : "f"(x));
    return r;
}
__device__ __forceinline__ void ldsm_x4(uint32_t& r0, uint32_t& r1, uint32_t& r2, uint32_t& r3, uint32_t addr) {
    asm volatile("ldmatrix.sync.aligned.m8n8.x4.shared.b16 {%0,%1,%2,%3}, [%4];\n"
        : "=r"(r0), "=r"(r1), "=r"(r2), "=r"(r3) : "r"(addr));
}
__device__ __forceinline__ void ldsm_x4_t(uint32_t& r0, uint32_t& r1, uint32_t& r2, uint32_t& r3, uint32_t addr) {
    asm volatile("ldmatrix.sync.aligned.m8n8.x4.trans.shared.b16 {%0,%1,%2,%3}, [%4];\n"
        : "=r"(r0), "=r"(r1), "=r"(r2), "=r"(r3) : "r"(addr));
}

// ---------------- bf16 tensor-core GEMM, 128x128 tile, BK=32, 3-stage, dist-2 prefetch ----------------
#define GBM 128
#define GBN 128
#define GBK 32
#define GNIT (DD / GBK)   // 24
#define NSTG 3
#define KSTR 40
#define A_ST (GBM * KSTR)
#define B_ST (GBN * KSTR)
#define GSMEM (NSTG * (A_ST + B_ST) * 2)  // 61440 bytes; 2 CTAs/SM fits (122880 < 227KB)

extern __shared__ char dyn_smem[];

template<bool RES>
__global__ __launch_bounds__(256, 2) void gemm_bf16_kernel(
    const bf16* __restrict__ A, const bf16* __restrict__ WtAll,
    const float* __restrict__ bias0, const float* __restrict__ bias1, const float* __restrict__ bias2,
    const float* __restrict__ res,
    bf16* __restrict__ C0, bf16* __restrict__ C1, bf16* __restrict__ C2,
    float* __restrict__ Cf)
{
    const int z = blockIdx.z;
    const bf16* Wt   = WtAll + (size_t)z * WSZ;
    const float* bias = (z == 0) ? bias0 : (z == 1) ? bias1 : bias2;
    bf16* Cb = (z == 0) ? C0 : (z == 1) ? C1 : C2;

    bf16* As = (bf16*)dyn_smem;
    bf16* Bs = As + NSTG * A_ST;

    const int tid = threadIdx.x;
    const int lane = tid & 31;
    const int wid = tid >> 5;
    const int g = lane >> 2;
    const int t = lane & 3;
    const int wm = (wid & 1) * 64;
    const int wn = (wid >> 1) * 32;
    const int rowBase = blockIdx.y * GBM;
    const int colBase = blockIdx.x * GBN;

    const int lsr = lane & 15;
    const int lsc = (lane >> 4) * 8;

    auto load_stage = [&](int st, int k0) {
        #pragma unroll
        for (int i = 0; i < 2; i++) {
            int idx = tid * 2 + i;
            int r = idx >> 2, ch = idx & 3;
            const bf16* ga = A + (size_t)(rowBase + r) * DD + k0 + ch * 8;
            uint32_t sa = (uint32_t)__cvta_generic_to_shared(&As[st * A_ST + r * KSTR + ch * 8]);
            cp16(sa, ga);
            const bf16* gb = Wt + (size_t)(colBase + r) * DD + k0 + ch * 8;
            uint32_t sb = (uint32_t)__cvta_generic_to_shared(&Bs[st * B_ST + r * KSTR + ch * 8]);
            cp16(sb, gb);
        }
    };

    float acc[4][4][4];
    #pragma unroll
    for (int i = 0; i < 4; i++)
        #pragma unroll
        for (int j = 0; j < 4; j++)
            #pragma unroll
            for (int r = 0; r < 4; r++) acc[i][j][r] = 0.f;

    load_stage(0, 0);
    cp_commit();
    load_stage(1, GBK);
    cp_commit();

    for (int it = 0; it < GNIT; it++) {
        if (it < GNIT - 1) cp_wait<1>();   // stage `it` done; `it+1` may be in flight
        else               cp_wait<0>();
        __syncthreads();                   // readers of stage (it+2)%3 finished last iter
        if (it + 2 < GNIT) {
            load_stage((it + 2) % NSTG, (it + 2) * GBK);
            cp_commit();
        }

        const bf16* Ast = As + (it % NSTG) * A_ST;
        const bf16* Bst = Bs + (it % NSTG) * B_ST;

        #pragma unroll
        for (int ks = 0; ks < 2; ks++) {
            int kb = ks * 16;
            uint32_t a[4][4];
            #pragma unroll
            for (int mi = 0; mi < 4; mi++) {
                uint32_t addr = (uint32_t)__cvta_generic_to_shared(
                    &Ast[(wm + mi * 16 + lsr) * KSTR + kb + lsc]);
                ldsm_x4(a[mi][0], a[mi][1], a[mi][2], a[mi][3], addr);
            }
            uint32_t b[4][2];
            #pragma unroll
            for (int np = 0; np < 2; np++) {
                uint32_t r0, r1, r2, r3;
                uint32_t addr = (uint32_t)__cvta_generic_to_shared(
                    &Bst[(wn + np * 16 + lsr) * KSTR + kb + lsc]);
                ldsm_x4(r0, r1, r2, r3, addr);
                b[2 * np    ][0] = r0; b[2 * np    ][1] = r2;
                b[2 * np + 1][0] = r1; b[2 * np + 1][1] = r3;
            }
            #pragma unroll
            for (int mi = 0; mi < 4; mi++)
                #pragma unroll
                for (int ni = 0; ni < 4; ni++)
                    mma_bf16(acc[mi][ni], a[mi], b[ni]);
        }
    }

    #pragma unroll
    for (int mi = 0; mi < 4; mi++) {
        #pragma unroll
        for (int rr = 0; rr < 2; rr++) {
            int row = rowBase + wm + mi * 16 + g + rr * 8;
            #pragma unroll
            for (int ni = 0; ni < 4; ni++) {
                int col = colBase + wn + ni * 8 + 2 * t;
                float c0 = acc[mi][ni][2 * rr + 0] + bias[col];
                float c1 = acc[mi][ni][2 * rr + 1] + bias[col + 1];
                if (RES) {
                    const float2 r2 = *(const float2*)&res[(size_t)row * DD + col];
                    c0 += r2.x; c1 += r2.y;
                    float2 o = {c0, c1};
                    *(float2*)&Cf[(size_t)row * DD + col] = o;
                } else {
                    __nv_bfloat162 h = __floats2bfloat162_rn(c0, c1);
                    *(__nv_bfloat162*)&Cb[(size_t)row * DD + col] = h;
                }
            }
        }
    }
}

// ---------------- banded attention: exp2, deferred-l, per-warp tile skip ----------------
#define ATS 72

__global__ __launch_bounds__(256) void attn_mma_kernel(
    const bf16* __restrict__ q, const bf16* __restrict__ k,
    const bf16* __restrict__ v, bf16* __restrict__ ctx)
{
    __shared__ bf16 Ks[2][64][ATS];
    __shared__ bf16 Vs[2][64][ATS];

    const int tid = threadIdx.x;
    const int lane = tid & 31;
    const int wid = tid >> 5;
    const int g = lane >> 2;
    const int t = lane & 3;
    const int wr = wid * 16;

    const int q0 = blockIdx.x * 128;
    const int h  = blockIdx.y;
    const int b  = blockIdx.z;
    const size_t bh_off = (size_t)b * SS * DD + h * DHH;
    const float qsc = 0.125f * 1.44269504089f;

    const int qg0 = q0 + wr + g;
    const int qg1 = qg0 + 8;

    uint32_t qa[4][4];
    {
        const bf16* r0p = q + bh_off + (size_t)qg0 * DD;
        const bf16* r1p = q + bh_off + (size_t)qg1 * DD;
        #pragma unroll
        for (int j = 0; j < 4; j++) {
            #pragma unroll
            for (int hh = 0; hh < 2; hh++) {
                const bf16* rp = hh ? r1p : r0p;
                #pragma unroll
                for (int cc = 0; cc < 2; cc++) {
                    __nv_bfloat162 pr = *(const __nv_bfloat162*)&rp[j * 16 + 2 * t + cc * 8];
                    float2 f = __bfloat1622float2(pr);
                    qa[j][hh + 2 * cc] = packbf(f.x * qsc, f.y * qsc);
                }
            }
        }
    }

    const int kstart = q0 - 256;
    const int jlo = (q0 < 256) ? (256 - q0) / 64 : 0;
    const int jhi = min(9, (SS + 192 - q0) / 64);

    auto prefetch = [&](int jt, int bu) {
        int kt0 = kstart + jt * 64;
        #pragma unroll
        for (int i = 0; i < 2; i++) {
            int idx = tid + i * 256;
            int r = idx >> 3, c8 = idx & 7;
            const bf16* base = k + bh_off + (size_t)(kt0 + r) * DD + c8 * 8;
            cp16((uint32_t)__cvta_generic_to_shared(&Ks[bu][r][c8 * 8]), base);
            const bf16* basev = v + bh_off + (size_t)(kt0 + r) * DD + c8 * 8;
            cp16((uint32_t)__cvta_generic_to_shared(&Vs[bu][r][c8 * 8]), basev);
        }
    };

    float o[8][4];
    #pragma unroll
    for (int ni = 0; ni < 8; ni++)
        #pragma unroll
        for (int r = 0; r < 4; r++) o[ni][r] = 0.f;
    float m0 = -1e30f, m1 = -1e30f, l0 = 0.f, l1 = 0.f;

    prefetch(jlo, 0);
    cp_commit();

    for (int jt = jlo; jt <= jhi; jt++) {
        const int bu = (jt - jlo) & 1;
        cp_wait<0>();
        __syncthreads();
        if (jt < jhi) {
            prefetch(jt + 1, bu ^ 1);
            cp_commit();
        }

        const int tk = jt * 64;
        if (tk <= wr + 527 && tk + 63 >= wr) {
            const int kt0 = kstart + tk;

            float s[8][4];
            #pragma unroll
            for (int ni = 0; ni < 8; ni++)
                s[ni][0] = s[ni][1] = s[ni][2] = s[ni][3] = 0.f;

            #pragma unroll
            for (int nn = 0; nn < 4; nn++) {
                #pragma unroll
                for (int j = 0; j < 4; j++) {
                    uint32_t r0, r1, r2, r3;
                    uint32_t addr = (uint32_t)__cvta_generic_to_shared(
                        &Ks[bu][nn * 16 + (lane & 15)][j * 16 + (lane >> 4) * 8]);
                    ldsm_x4(r0, r1, r2, r3, addr);
                    uint32_t b0[2] = {r0, r2};
                    uint32_t b1[2] = {r1, r3};
                    mma_bf16(s[2 * nn    ], qa[j], b0);
                    mma_bf16(s[2 * nn + 1], qa[j], b1);
                }
            }

            if (jt <= 1 || jt >= 8) {
                #pragma unroll
                for (int ni = 0; ni < 8; ni++) {
                    int kg = kt0 + ni * 8 + 2 * t;
                    if (kg < qg0 - W1C || kg > qg0 + W1C) s[ni][0] = -1e30f;
                    if (kg + 1 < qg0 - W1C || kg + 1 > qg0 + W1C) s[ni][1] = -1e30f;
                    if (kg < qg1 - W1C || kg > qg1 + W1C) s[ni][2] = -1e30f;
                    if (kg + 1 < qg1 - W1C || kg + 1 > qg1 + W1C) s[ni][3] = -1e30f;
                }
            }

            {
                float mx0 = -1e30f, mx1 = -1e30f;
                #pragma unroll
                for (int ni = 0; ni < 8; ni++) {
                    mx0 = fmaxf(mx0, fmaxf(s[ni][0], s[ni][1]));
                    mx1 = fmaxf(mx1, fmaxf(s[ni][2], s[ni][3]));
                }
                mx0 = fmaxf(mx0, __shfl_xor_sync(0xffffffffu, mx0, 1));
                mx0 = fmaxf(mx0, __shfl_xor_sync(0xffffffffu, mx0, 2));
                mx1 = fmaxf(mx1, __shfl_xor_sync(0xffffffffu, mx1, 1));
                mx1 = fmaxf(mx1, __shfl_xor_sync(0xffffffffu, mx1, 2));
                float nm0 = fmaxf(m0, mx0), nm1 = fmaxf(m1, mx1);
                float cor0 = ex2(m0 - nm0), cor1 = ex2(m1 - nm1);
                float rs0 = 0.f, rs1 = 0.f;
                #pragma unroll
                for (int ni = 0; ni < 8; ni++) {
                    s[ni][0] = ex2(s[ni][0] - nm0);
                    s[ni][1] = ex2(s[ni][1] - nm0);
                    s[ni][2] = ex2(s[ni][2] - nm1);
                    s[ni][3] = ex2(s[ni][3] - nm1);
                    rs0 += s[ni][0] + s[ni][1];
                    rs1 += s[ni][2] + s[ni][3];
                    o[ni][0] *= cor0; o[ni][1] *= cor0;
                    o[ni][2] *= cor1; o[ni][3] *= cor1;
                }
                l0 = l0 * cor0 + rs0;
                l1 = l1 * cor1 + rs1;
                m0 = nm0; m1 = nm1;
            }

            #pragma unroll
            for (int j = 0; j < 4; j++) {
                uint32_t a[4];
                a[0] = packbf(s[2 * j    ][0], s[2 * j    ][1]);
                a[1] = packbf(s[2 * j    ][2], s[2 * j    ][3]);
                a[2] = packbf(s[2 * j + 1][0], s[2 * j + 1][1]);
                a[3] = packbf(s[2 * j + 1][2], s[2 * j + 1][3]);
                #pragma unroll
                for (int nn = 0; nn < 4; nn++) {
                    uint32_t r0, r1, r2, r3;
                    uint32_t addr = (uint32_t)__cvta_generic_to_shared(
                        &Vs[bu][j * 16 + (lane & 15)][nn * 16 + (lane >> 4) * 8]);
                    ldsm_x4_t(r0, r1, r2, r3, addr);
                    uint32_t b0[2] = {r0, r1};
                    uint32_t b1[2] = {r2, r3};
                    mma_bf16(o[2 * nn    ], a, b0);
                    mma_bf16(o[2 * nn + 1], a, b1);
                }
            }
        }
    }

    l0 += __shfl_xor_sync(0xffffffffu, l0, 1);
    l0 += __shfl_xor_sync(0xffffffffu, l0, 2);
    l1 += __shfl_xor_sync(0xffffffffu, l1, 1);
    l1 += __shfl_xor_sync(0xffffffffu, l1, 2);
    float inv0 = 1.0f / l0, inv1 = 1.0f / l1;
    #pragma unroll
    for (int ni = 0; ni < 8; ni++) {
        int col = ni * 8 + 2 * t;
        __nv_bfloat162 w0 = __floats2bfloat162_rn(o[ni][0] * inv0, o[ni][1] * inv0);
        __nv_bfloat162 w1 = __floats2bfloat162_rn(o[ni][2] * inv1, o[ni][3] * inv1);
        *(__nv_bfloat162*)(ctx + bh_off + (size_t)qg0 * DD + col) = w0;
        *(__nv_bfloat162*)(ctx + bh_off + (size_t)qg1 * DD + col) = w1;
    }
}

// ---------------- launch ----------------
extern "C" void kernel_launch(void* const* d_in, const int* in_sizes, int n_in,
                              void* d_out, int out_size)
{
    const int*   ids    = (const int*)  d_in[0];
    const float* state  = (const float*)d_in[1];
    const float* wemb   = (const float*)d_in[2];
    const float* pemb   = (const float*)d_in[3];
    const float* ln_e_g = (const float*)d_in[4];
    const float* ln_e_b = (const float*)d_in[5];
    const float* Wq     = (const float*)d_in[6];
    const float* bq     = (const float*)d_in[7];
    const float* Wk     = (const float*)d_in[8];
    const float* bk     = (const float*)d_in[9];
    const float* Wv     = (const float*)d_in[10];
    const float* bv     = (const float*)d_in[11];
    const float* Wo     = (const float*)d_in[12];
    const float* bo     = (const float*)d_in[13];
    const float* ln_a_g = (const float*)d_in[14];
    const float* ln_a_b = (const float*)d_in[15];
    float* out = (float*)d_out;

    float *x, *hx;  bf16 *xb, *qb, *kb, *vb, *cb, *wt;
    cudaGetSymbolAddress((void**)&x,  g_x);
    cudaGetSymbolAddress((void**)&hx, g_h);
    cudaGetSymbolAddress((void**)&xb, g_xb);
    cudaGetSymbolAddress((void**)&qb, g_qb);
    cudaGetSymbolAddress((void**)&kb, g_kb);
    cudaGetSymbolAddress((void**)&vb, g_vb);
    cudaGetSymbolAddress((void**)&cb, g_cb);
    cudaGetSymbolAddress((void**)&wt, g_wt);

    static int smem_set = 0;
    if (!smem_set) {
        cudaFuncSetAttribute(gemm_bf16_kernel<false>,
                             cudaFuncAttributeMaxDynamicSharedMemorySize, GSMEM);
        cudaFuncSetAttribute(gemm_bf16_kernel<true>,
                             cudaFuncAttributeMaxDynamicSharedMemorySize, GSMEM);
        smem_set = 1;
    }

    embed_wtrans_kernel<<<EMB_BLOCKS + WT_BLOCKS, 256>>>(
        ids, wemb, pemb, ln_e_g, ln_e_b, x, xb, Wq, Wk, Wv, Wo, wt);

    dim3 gqkv(DD / GBN, MTOK / 128, 3);   // (6, 64, 3)
    gemm_bf16_kernel<false><<<gqkv, 256, GSMEM>>>(
        xb, wt, bq, bk, bv, nullptr, qb, kb, vb, nullptr);

    attn_mma_kernel<<<dim3(SS / 128, HH, BB), 256>>>(qb, kb, vb, cb);

    dim3 go(DD / GBN, MTOK / 128, 1);     // (6, 64, 1)
    gemm_bf16_kernel<true><<<go, 256, GSMEM>>>(
        cb, wt + 3 * (size_t)WSZ, bo, bo, bo, x, nullptr, nullptr, nullptr, hx);

    ln_kernel<<<MTOK / 8, 256>>>(hx, ln_a_g, ln_a_b, out);

    long long tail = (long long)out_size - (long long)MTOK * DD;
    if (tail > 0) {
        cudaMemcpyAsync(out + (size_t)MTOK * DD, state,
                        (size_t)tail * sizeof(float),
                        cudaMemcpyDeviceToDevice);
    }
}

// round 16
// speedup vs baseline: 1.0529x; 1.0529x over previous
#include <cuda_runtime.h>
#include <cuda_bf16.h>
#include <math.h>
#include <stdint.h>

#define BB 2
#define SS 4096
#define DD 768
#define HH 12
#define DHH 64
#define W1C 256
#define MTOK (BB*SS)   // 8192
#define WSZ (DD*DD)

typedef __nv_bfloat16 bf16;

// ---------------- scratch (device globals; no allocation allowed) ----------------
__device__ __align__(16) float g_x [MTOK*DD];
__device__ __align__(16) float g_h [MTOK*DD];
__device__ __align__(16) bf16  g_xb [MTOK*DD];
__device__ __align__(16) bf16  g_qb [MTOK*DD];
__device__ __align__(16) bf16  g_kb [MTOK*DD];
__device__ __align__(16) bf16  g_vb [MTOK*DD];
__device__ __align__(16) bf16  g_cb [MTOK*DD];
__device__ __align__(16) bf16  g_wt [4*WSZ];

// ---------------- fused: embedding+LN (warp/token) | weight transpose ----------------
#define EMB_BLOCKS (MTOK / 8)    // 1024
#define WT_BLOCKS  (24*24*4)     // 2304

__global__ __launch_bounds__(256) void embed_wtrans_kernel(
    const int* __restrict__ ids, const float* __restrict__ wemb,
    const float* __restrict__ pemb, const float* __restrict__ g,
    const float* __restrict__ b, float* __restrict__ x, bf16* __restrict__ xb,
    const float* __restrict__ W0, const float* __restrict__ W1,
    const float* __restrict__ W2, const float* __restrict__ W3,
    bf16* __restrict__ wt)
{
    __shared__ float tile[32][33];
    const int lane = threadIdx.x & 31;
    const int wid  = threadIdx.x >> 5;
    if (blockIdx.x < EMB_BLOCKS) {
        int tok = blockIdx.x * 8 + wid;
        int s_pos = tok & (SS - 1);
        int id = ids[tok];
        const float* we = wemb + (size_t)id * DD;
        const float* pe = pemb + (size_t)s_pos * DD;
        float v[24]; float sum = 0.f, sum2 = 0.f;
        #pragma unroll
        for (int i = 0; i < 24; i++) {
            int d = lane + i * 32;
            v[i] = we[d] + pe[d];
            sum += v[i]; sum2 += v[i] * v[i];
        }
        #pragma unroll
        for (int o = 16; o > 0; o >>= 1) {
            sum  += __shfl_xor_sync(0xffffffffu, sum,  o);
            sum2 += __shfl_xor_sync(0xffffffffu, sum2, o);
        }
        float mean = sum * (1.0f / DD);
        float var  = sum2 * (1.0f / DD) - mean * mean;
        float rstd = rsqrtf(var + 1e-5f);
        float* row = x + (size_t)tok * DD;
        bf16*  rowb = xb + (size_t)tok * DD;
        #pragma unroll
        for (int i = 0; i < 24; i++) {
            int d = lane + i * 32;
            float o = (v[i] - mean) * rstd * g[d] + b[d];
            row[d] = o;
            rowb[d] = __float2bfloat16(o);
        }
    } else {
        int bx = blockIdx.x - EMB_BLOCKS;
        int w  = bx / 576;
        int rem = bx % 576;
        int k0 = (rem / 24) * 32;
        int n0 = (rem % 24) * 32;
        const float* W = (w == 0) ? W0 : (w == 1) ? W1 : (w == 2) ? W2 : W3;
        bf16* dst = wt + (size_t)w * WSZ;
        int tx = lane, ty = wid;
        #pragma unroll
        for (int i = 0; i < 4; i++)
            tile[ty + i * 8][tx] = W[(size_t)(k0 + ty + i * 8) * DD + n0 + tx];
        __syncthreads();
        #pragma unroll
        for (int i = 0; i < 4; i++)
            dst[(size_t)(n0 + ty + i * 8) * DD + k0 + tx] = __float2bfloat16(tile[tx][ty + i * 8]);
    }
}

// ---------------- final layernorm (warp per token) ----------------
__global__ __launch_bounds__(256) void ln_kernel(
    const float* __restrict__ in, const float* __restrict__ g,
    const float* __restrict__ b, float* __restrict__ out)
{
    const int lane = threadIdx.x & 31;
    const int wid  = threadIdx.x >> 5;
    int tok = blockIdx.x * 8 + wid;
    const float* row = in + (size_t)tok * DD;
    float v[24]; float sum = 0.f, sum2 = 0.f;
    #pragma unroll
    for (int i = 0; i < 24; i++) {
        int d = lane + i * 32;
        v[i] = row[d];
        sum += v[i]; sum2 += v[i] * v[i];
    }
    #pragma unroll
    for (int o = 16; o > 0; o >>= 1) {
        sum  += __shfl_xor_sync(0xffffffffu, sum,  o);
        sum2 += __shfl_xor_sync(0xffffffffu, sum2, o);
    }
    float mean = sum * (1.0f / DD);
    float var  = sum2 * (1.0f / DD) - mean * mean;
    float rstd = rsqrtf(var + 1e-5f);
    float* orow = out + (size_t)tok * DD;
    #pragma unroll
    for (int i = 0; i < 24; i++) {
        int d = lane + i * 32;
        orow[d] = (v[i] - mean) * rstd * g[d] + b[d];
    }
}

// ---------------- async copy + mma + ldmatrix helpers ----------------
__device__ __forceinline__ void cp16(uint32_t smem, const void* gmem) {
    asm volatile("cp.async.cg.shared.global [%0], [%1], 16;\n" :: "r"(smem), "l"(gmem));
}
__device__ __forceinline__ void cp16ca(uint32_t smem, const void* gmem) {
    asm volatile("cp.async.ca.shared.global [%0], [%1], 16;\n" :: "r"(smem), "l"(gmem));
}
__device__ __forceinline__ void cp_commit() { asm volatile("cp.async.commit_group;\n"); }
template<int N>
__device__ __forceinline__ void cp_wait() { asm volatile("cp.async.wait_group %0;\n" :: "n"(N)); }

__device__ __forceinline__ void mma_bf16(float* c, const uint32_t* a, const uint32_t* b) {
    asm volatile(
        "mma.sync.aligned.m16n8k16.row.col.f32.bf16.bf16.f32 "
        "{%0,%1,%2,%3}, {%4,%5,%6,%7}, {%8,%9}, {%0,%1,%2,%3};\n"
        : "+f"(c[0]), "+f"(c[1]), "+f"(c[2]), "+f"(c[3])
        : "r"(a[0]), "r"(a[1]), "r"(a[2]), "r"(a[3]), "r"(b[0]), "r"(b[1]));
}
__device__ __forceinline__ uint32_t packbf(float x, float y) {
    __nv_bfloat162 h = __floats2bfloat162_rn(x, y);
    return *(uint32_t*)&h;
}
__device__ __forceinline__ float ex2(float x) {
    float r;
    asm("ex2.approx.f32 %0, %1;" : "=f"(r) : "f"(x));
    return r;
}
__device__ __forceinline__ void ldsm_x4(uint32_t& r0, uint32_t& r1, uint32_t& r2, uint32_t& r3, uint32_t addr) {
    asm volatile("ldmatrix.sync.aligned.m8n8.x4.shared.b16 {%0,%1,%2,%3}, [%4];\n"
        : "=r"(r0), "=r"(r1), "=r"(r2), "=r"(r3) : "r"(addr));
}
__device__ __forceinline__ void ldsm_x4_t(uint32_t& r0, uint32_t& r1, uint32_t& r2, uint32_t& r3, uint32_t addr) {
    asm volatile("ldmatrix.sync.aligned.m8n8.x4.trans.shared.b16 {%0,%1,%2,%3}, [%4];\n"
        : "=r"(r0), "=r"(r1), "=r"(r2), "=r"(r3) : "r"(addr));
}

// ---------------- bf16 tensor-core GEMM, 128x128 tile, BK=32, 2-stage, 2 CTAs/SM ----------------
#define GBM 128
#define GBN 128
#define GBK 32
#define GNIT (DD / GBK)   // 24
#define NSTG 2
#define KSTR 40
#define A_ST (GBM * KSTR)
#define B_ST (GBN * KSTR)
#define GSMEM (NSTG * (A_ST + B_ST) * 2)  // 40960 bytes

extern __shared__ char dyn_smem[];

template<bool RES>
__global__ __launch_bounds__(256, 2) void gemm_bf16_kernel(
    const bf16* __restrict__ A, const bf16* __restrict__ WtAll,
    const float* __restrict__ bias0, const float* __restrict__ bias1, const float* __restrict__ bias2,
    const float* __restrict__ res,
    bf16* __restrict__ C0, bf16* __restrict__ C1, bf16* __restrict__ C2,
    float* __restrict__ Cf)
{
    const int z = blockIdx.z;
    const bf16* Wt   = WtAll + (size_t)z * WSZ;
    const float* bias = (z == 0) ? bias0 : (z == 1) ? bias1 : bias2;
    bf16* Cb = (z == 0) ? C0 : (z == 1) ? C1 : C2;

    bf16* As = (bf16*)dyn_smem;
    bf16* Bs = As + NSTG * A_ST;

    const int tid = threadIdx.x;
    const int lane = tid & 31;
    const int wid = tid >> 5;
    const int g = lane >> 2;
    const int t = lane & 3;
    const int wm = (wid & 1) * 64;
    const int wn = (wid >> 1) * 32;
    const int rowBase = blockIdx.y * GBM;
    const int colBase = blockIdx.x * GBN;

    const int lsr = lane & 15;
    const int lsc = (lane >> 4) * 8;

    auto load_stage = [&](int st, int k0) {
        #pragma unroll
        for (int i = 0; i < 2; i++) {
            int idx = tid * 2 + i;
            int r = idx >> 2, ch = idx & 3;
            const bf16* ga = A + (size_t)(rowBase + r) * DD + k0 + ch * 8;
            uint32_t sa = (uint32_t)__cvta_generic_to_shared(&As[st * A_ST + r * KSTR + ch * 8]);
            cp16(sa, ga);                                  // A: streamed, L1-bypass
            const bf16* gb = Wt + (size_t)(colBase + r) * DD + k0 + ch * 8;
            uint32_t sb = (uint32_t)__cvta_generic_to_shared(&Bs[st * B_ST + r * KSTR + ch * 8]);
            cp16ca(sb, gb);                                // B: weights, L1-cached (cross-CTA reuse)
        }
    };

    float acc[4][4][4];
    #pragma unroll
    for (int i = 0; i < 4; i++)
        #pragma unroll
        for (int j = 0; j < 4; j++)
            #pragma unroll
            for (int r = 0; r < 4; r++) acc[i][j][r] = 0.f;

    load_stage(0, 0);
    cp_commit();

    for (int it = 0; it < GNIT; it++) {
        cp_wait<0>();
        __syncthreads();
        if (it + 1 < GNIT) {
            load_stage((it + 1) & 1, (it + 1) * GBK);
            cp_commit();
        }

        const bf16* Ast = As + (it & 1) * A_ST;
        const bf16* Bst = Bs + (it & 1) * B_ST;

        #pragma unroll
        for (int ks = 0; ks < 2; ks++) {
            int kb = ks * 16;
            uint32_t a[4][4];
            #pragma unroll
            for (int mi = 0; mi < 4; mi++) {
                uint32_t addr = (uint32_t)__cvta_generic_to_shared(
                    &Ast[(wm + mi * 16 + lsr) * KSTR + kb + lsc]);
                ldsm_x4(a[mi][0], a[mi][1], a[mi][2], a[mi][3], addr);
            }
            uint32_t b[4][2];
            #pragma unroll
            for (int np = 0; np < 2; np++) {
                uint32_t r0, r1, r2, r3;
                uint32_t addr = (uint32_t)__cvta_generic_to_shared(
                    &Bst[(wn + np * 16 + lsr) * KSTR + kb + lsc]);
                ldsm_x4(r0, r1, r2, r3, addr);
                b[2 * np    ][0] = r0; b[2 * np    ][1] = r2;
                b[2 * np + 1][0] = r1; b[2 * np + 1][1] = r3;
            }
            #pragma unroll
            for (int mi = 0; mi < 4; mi++)
                #pragma unroll
                for (int ni = 0; ni < 4; ni++)
                    mma_bf16(acc[mi][ni], a[mi], b[ni]);
        }
    }

    #pragma unroll
    for (int mi = 0; mi < 4; mi++) {
        #pragma unroll
        for (int rr = 0; rr < 2; rr++) {
            int row = rowBase + wm + mi * 16 + g + rr * 8;
            #pragma unroll
            for (int ni = 0; ni < 4; ni++) {
                int col = colBase + wn + ni * 8 + 2 * t;
                float c0 = acc[mi][ni][2 * rr + 0] + bias[col];
                float c1 = acc[mi][ni][2 * rr + 1] + bias[col + 1];
                if (RES) {
                    const float2 r2 = *(const float2*)&res[(size_t)row * DD + col];
                    c0 += r2.x; c1 += r2.y;
                    float2 o = {c0, c1};
                    *(float2*)&Cf[(size_t)row * DD + col] = o;
                } else {
                    __nv_bfloat162 h = __floats2bfloat162_rn(c0, c1);
                    *(__nv_bfloat162*)&Cb[(size_t)row * DD + col] = h;
                }
            }
        }
    }
}

// ---------------- banded attention: exp2, deferred-l, per-warp tile skip ----------------
#define ATS 72

__global__ __launch_bounds__(256) void attn_mma_kernel(
    const bf16* __restrict__ q, const bf16* __restrict__ k,
    const bf16* __restrict__ v, bf16* __restrict__ ctx)
{
    __shared__ bf16 Ks[2][64][ATS];
    __shared__ bf16 Vs[2][64][ATS];

    const int tid = threadIdx.x;
    const int lane = tid & 31;
    const int wid = tid >> 5;
    const int g = lane >> 2;
    const int t = lane & 3;
    const int wr = wid * 16;

    const int q0 = blockIdx.x * 128;
    const int h  = blockIdx.y;
    const int b  = blockIdx.z;
    const size_t bh_off = (size_t)b * SS * DD + h * DHH;
    const float qsc = 0.125f * 1.44269504089f;

    const int qg0 = q0 + wr + g;
    const int qg1 = qg0 + 8;

    uint32_t qa[4][4];
    {
        const bf16* r0p = q + bh_off + (size_t)qg0 * DD;
        const bf16* r1p = q + bh_off + (size_t)qg1 * DD;
        #pragma unroll
        for (int j = 0; j < 4; j++) {
            #pragma unroll
            for (int hh = 0; hh < 2; hh++) {
                const bf16* rp = hh ? r1p : r0p;
                #pragma unroll
                for (int cc = 0; cc < 2; cc++) {
                    __nv_bfloat162 pr = *(const __nv_bfloat162*)&rp[j * 16 + 2 * t + cc * 8];
                    float2 f = __bfloat1622float2(pr);
                    qa[j][hh + 2 * cc] = packbf(f.x * qsc, f.y * qsc);
                }
            }
        }
    }

    const int kstart = q0 - 256;
    const int jlo = (q0 < 256) ? (256 - q0) / 64 : 0;
    const int jhi = min(9, (SS + 192 - q0) / 64);

    auto prefetch = [&](int jt, int bu) {
        int kt0 = kstart + jt * 64;
        #pragma unroll
        for (int i = 0; i < 2; i++) {
            int idx = tid + i * 256;
            int r = idx >> 3, c8 = idx & 7;
            const bf16* base = k + bh_off + (size_t)(kt0 + r) * DD + c8 * 8;
            cp16((uint32_t)__cvta_generic_to_shared(&Ks[bu][r][c8 * 8]), base);
            const bf16* basev = v + bh_off + (size_t)(kt0 + r) * DD + c8 * 8;
            cp16((uint32_t)__cvta_generic_to_shared(&Vs[bu][r][c8 * 8]), basev);
        }
    };

    float o[8][4];
    #pragma unroll
    for (int ni = 0; ni < 8; ni++)
        #pragma unroll
        for (int r = 0; r < 4; r++) o[ni][r] = 0.f;
    float m0 = -1e30f, m1 = -1e30f, l0 = 0.f, l1 = 0.f;

    prefetch(jlo, 0);
    cp_commit();

    for (int jt = jlo; jt <= jhi; jt++) {
        const int bu = (jt - jlo) & 1;
        cp_wait<0>();
        __syncthreads();
        if (jt < jhi) {
            prefetch(jt + 1, bu ^ 1);
            cp_commit();
        }

        const int tk = jt * 64;
        if (tk <= wr + 527 && tk + 63 >= wr) {
            const int kt0 = kstart + tk;

            float s[8][4];
            #pragma unroll
            for (int ni = 0; ni < 8; ni++)
                s[ni][0] = s[ni][1] = s[ni][2] = s[ni][3] = 0.f;

            #pragma unroll
            for (int nn = 0; nn < 4; nn++) {
                #pragma unroll
                for (int j = 0; j < 4; j++) {
                    uint32_t r0, r1, r2, r3;
                    uint32_t addr = (uint32_t)__cvta_generic_to_shared(
                        &Ks[bu][nn * 16 + (lane & 15)][j * 16 + (lane >> 4) * 8]);
                    ldsm_x4(r0, r1, r2, r3, addr);
                    uint32_t b0[2] = {r0, r2};
                    uint32_t b1[2] = {r1, r3};
                    mma_bf16(s[2 * nn    ], qa[j], b0);
                    mma_bf16(s[2 * nn + 1], qa[j], b1);
                }
            }

            if (jt <= 1 || jt >= 8) {
                #pragma unroll
                for (int ni = 0; ni < 8; ni++) {
                    int kg = kt0 + ni * 8 + 2 * t;
                    if (kg < qg0 - W1C || kg > qg0 + W1C) s[ni][0] = -1e30f;
                    if (kg + 1 < qg0 - W1C || kg + 1 > qg0 + W1C) s[ni][1] = -1e30f;
                    if (kg < qg1 - W1C || kg > qg1 + W1C) s[ni][2] = -1e30f;
                    if (kg + 1 < qg1 - W1C || kg + 1 > qg1 + W1C) s[ni][3] = -1e30f;
                }
            }

            {
                float mx0 = -1e30f, mx1 = -1e30f;
                #pragma unroll
                for (int ni = 0; ni < 8; ni++) {
                    mx0 = fmaxf(mx0, fmaxf(s[ni][0], s[ni][1]));
                    mx1 = fmaxf(mx1, fmaxf(s[ni][2], s[ni][3]));
                }
                mx0 = fmaxf(mx0, __shfl_xor_sync(0xffffffffu, mx0, 1));
                mx0 = fmaxf(mx0, __shfl_xor_sync(0xffffffffu, mx0, 2));
                mx1 = fmaxf(mx1, __shfl_xor_sync(0xffffffffu, mx1, 1));
                mx1 = fmaxf(mx1, __shfl_xor_sync(0xffffffffu, mx1, 2));
                float nm0 = fmaxf(m0, mx0), nm1 = fmaxf(m1, mx1);
                float cor0 = ex2(m0 - nm0), cor1 = ex2(m1 - nm1);
                float rs0 = 0.f, rs1 = 0.f;
                #pragma unroll
                for (int ni = 0; ni < 8; ni++) {
                    s[ni][0] = ex2(s[ni][0] - nm0);
                    s[ni][1] = ex2(s[ni][1] - nm0);
                    s[ni][2] = ex2(s[ni][2] - nm1);
                    s[ni][3] = ex2(s[ni][3] - nm1);
                    rs0 += s[ni][0] + s[ni][1];
                    rs1 += s[ni][2] + s[ni][3];
                    o[ni][0] *= cor0; o[ni][1] *= cor0;
                    o[ni][2] *= cor1; o[ni][3] *= cor1;
                }
                l0 = l0 * cor0 + rs0;
                l1 = l1 * cor1 + rs1;
                m0 = nm0; m1 = nm1;
            }

            #pragma unroll
            for (int j = 0; j < 4; j++) {
                uint32_t a[4];
                a[0] = packbf(s[2 * j    ][0], s[2 * j    ][1]);
                a[1] = packbf(s[2 * j    ][2], s[2 * j    ][3]);
                a[2] = packbf(s[2 * j + 1][0], s[2 * j + 1][1]);
                a[3] = packbf(s[2 * j + 1][2], s[2 * j + 1][3]);
                #pragma unroll
                for (int nn = 0; nn < 4; nn++) {
                    uint32_t r0, r1, r2, r3;
                    uint32_t addr = (uint32_t)__cvta_generic_to_shared(
                        &Vs[bu][j * 16 + (lane & 15)][nn * 16 + (lane >> 4) * 8]);
                    ldsm_x4_t(r0, r1, r2, r3, addr);
                    uint32_t b0[2] = {r0, r1};
                    uint32_t b1[2] = {r2, r3};
                    mma_bf16(o[2 * nn    ], a, b0);
                    mma_bf16(o[2 * nn + 1], a, b1);
                }
            }
        }
    }

    l0 += __shfl_xor_sync(0xffffffffu, l0, 1);
    l0 += __shfl_xor_sync(0xffffffffu, l0, 2);
    l1 += __shfl_xor_sync(0xffffffffu, l1, 1);
    l1 += __shfl_xor_sync(0xffffffffu, l1, 2);
    float inv0 = 1.0f / l0, inv1 = 1.0f / l1;
    #pragma unroll
    for (int ni = 0; ni < 8; ni++) {
        int col = ni * 8 + 2 * t;
        __nv_bfloat162 w0 = __floats2bfloat162_rn(o[ni][0] * inv0, o[ni][1] * inv0);
        __nv_bfloat162 w1 = __floats2bfloat162_rn(o[ni][2] * inv1, o[ni][3] * inv1);
        *(__nv_bfloat162*)(ctx + bh_off + (size_t)qg0 * DD + col) = w0;
        *(__nv_bfloat162*)(ctx + bh_off + (size_t)qg1 * DD + col) = w1;
    }
}

// ---------------- launch ----------------
extern "C" void kernel_launch(void* const* d_in, const int* in_sizes, int n_in,
                              void* d_out, int out_size)
{
    const int*   ids    = (const int*)  d_in[0];
    const float* state  = (const float*)d_in[1];
    const float* wemb   = (const float*)d_in[2];
    const float* pemb   = (const float*)d_in[3];
    const float* ln_e_g = (const float*)d_in[4];
    const float* ln_e_b = (const float*)d_in[5];
    const float* Wq     = (const float*)d_in[6];
    const float* bq     = (const float*)d_in[7];
    const float* Wk     = (const float*)d_in[8];
    const float* bk     = (const float*)d_in[9];
    const float* Wv     = (const float*)d_in[10];
    const float* bv     = (const float*)d_in[11];
    const float* Wo     = (const float*)d_in[12];
    const float* bo     = (const float*)d_in[13];
    const float* ln_a_g = (const float*)d_in[14];
    const float* ln_a_b = (const float*)d_in[15];
    float* out = (float*)d_out;

    float *x, *hx;  bf16 *xb, *qb, *kb, *vb, *cb, *wt;
    cudaGetSymbolAddress((void**)&x,  g_x);
    cudaGetSymbolAddress((void**)&hx, g_h);
    cudaGetSymbolAddress((void**)&xb, g_xb);
    cudaGetSymbolAddress((void**)&qb, g_qb);
    cudaGetSymbolAddress((void**)&kb, g_kb);
    cudaGetSymbolAddress((void**)&vb, g_vb);
    cudaGetSymbolAddress((void**)&cb, g_cb);
    cudaGetSymbolAddress((void**)&wt, g_wt);

    static int smem_set = 0;
    if (!smem_set) {
        cudaFuncSetAttribute(gemm_bf16_kernel<false>,
                             cudaFuncAttributeMaxDynamicSharedMemorySize, GSMEM);
        cudaFuncSetAttribute(gemm_bf16_kernel<true>,
                             cudaFuncAttributeMaxDynamicSharedMemorySize, GSMEM);
        smem_set = 1;
    }

    embed_wtrans_kernel<<<EMB_BLOCKS + WT_BLOCKS, 256>>>(
        ids, wemb, pemb, ln_e_g, ln_e_b, x, xb, Wq, Wk, Wv, Wo, wt);

    dim3 gqkv(DD / GBN, MTOK / 128, 3);   // (6, 64, 3)
    gemm_bf16_kernel<false><<<gqkv, 256, GSMEM>>>(
        xb, wt, bq, bk, bv, nullptr, qb, kb, vb, nullptr);

    attn_mma_kernel<<<dim3(SS / 128, HH, BB), 256>>>(qb, kb, vb, cb);

    dim3 go(DD / GBN, MTOK / 128, 1);     // (6, 64, 1)
    gemm_bf16_kernel<true><<<go, 256, GSMEM>>>(
        cb, wt + 3 * (size_t)WSZ, bo, bo, bo, x, nullptr, nullptr, nullptr, hx);

    ln_kernel<<<MTOK / 8, 256>>>(hx, ln_a_g, ln_a_b, out);

    long long tail = (long long)out_size - (long long)MTOK * DD;
    if (tail > 0) {
        cudaMemcpyAsync(out + (size_t)MTOK * DD, state,
                        (size_t)tail * sizeof(float),
                        cudaMemcpyDeviceToDevice);
    }
}